// round 3
// baseline (speedup 1.0000x reference)
#include <cuda_runtime.h>

// Geometry
#define HH   512
#define W4   128           // 512 floats / 4 per quad
#define TC   6             // t-chunks
#define TPC  33            // 198 / 6
#define GX   4             // 128 quads / 32 lanes
#define GY   32            // 512 rows / (8 warps * 2 rows)
#define NBLK (GX*GY*TC)    // 768

#define DENOM 52107462.0   // 198 * 513 * 513

typedef unsigned long long u64;

__device__ float g_part[NBLK * 2];
__device__ unsigned int g_count = 0;

// ---------- packed f32x2 helpers ----------
__device__ __forceinline__ u64 pk(float a, float b) {
    u64 r; asm("mov.b64 %0, {%1, %2};" : "=l"(r) : "f"(a), "f"(b)); return r;
}
__device__ __forceinline__ void upk(u64 v, float& a, float& b) {
    asm("mov.b64 {%0, %1}, %2;" : "=f"(a), "=f"(b) : "l"(v));
}
__device__ __forceinline__ u64 fadd2(u64 a, u64 b) {
    u64 d; asm("add.rn.f32x2 %0, %1, %2;" : "=l"(d) : "l"(a), "l"(b)); return d;
}
__device__ __forceinline__ u64 fsub2(u64 a, u64 b) {
    u64 d; asm("sub.rn.f32x2 %0, %1, %2;" : "=l"(d) : "l"(a), "l"(b)); return d;
}
__device__ __forceinline__ u64 fmul2(u64 a, u64 b) {
    u64 d; asm("mul.rn.f32x2 %0, %1, %2;" : "=l"(d) : "l"(a), "l"(b)); return d;
}
__device__ __forceinline__ u64 ffma2(u64 a, u64 b, u64 c) {
    u64 d; asm("fma.rn.f32x2 %0, %1, %2, %3;" : "=l"(d) : "l"(a), "l"(b), "l"(c)); return d;
}

// Laplacian (MU-folded) and time-difference for one channel-row.
__device__ __forceinline__ void lap_d(
    u64 clo, u64 chi, u64 lhi, u64 rlo,
    u64 n1lo, u64 n1hi, u64 p1lo, u64 p1hi,
    u64 n2lo, u64 n2hi, u64 p2lo, u64 p2hi,
    u64 nxlo, u64 nxhi,
    u64 CC, u64 CN, u64 CF,
    u64& laplo, u64& laphi, u64& dlo, u64& dhi)
{
    float c0, c1, c2, c3, lz, lw, r0, r1;
    upk(clo, c0, c1); upk(chi, c2, c3); upk(lhi, lz, lw); upk(rlo, r0, r1);
    const u64 m1 = pk(lw, c0);
    const u64 m2 = pk(c1, c2);
    const u64 m3 = pk(c3, r0);
    const u64 njlo = fadd2(m1, m2),  njhi = fadd2(m2, m3);
    const u64 fjlo = fadd2(lhi, chi), fjhi = fadd2(clo, rlo);
    const u64 nilo = fadd2(n1lo, p1lo), nihi = fadd2(n1hi, p1hi);
    const u64 filo = fadd2(n2lo, p2lo), fihi = fadd2(n2hi, p2hi);
    const u64 nearlo = fadd2(njlo, nilo), nearhi = fadd2(njhi, nihi);
    const u64 farlo  = fadd2(fjlo, filo), farhi  = fadd2(fjhi, fihi);
    laplo = ffma2(CN, nearlo, ffma2(CF, farlo, fmul2(CC, clo)));
    laphi = ffma2(CN, nearhi, ffma2(CF, farhi, fmul2(CC, chi)));
    dlo = fsub2(nxlo, clo);
    dhi = fsub2(nxhi, chi);
}

// Residuals for one row (both channels). Outputs packed residual pairs.
__device__ __forceinline__ void row_res(
    ulonglong2 uc, ulonglong2 vc,
    u64 ul, u64 ur, u64 vl, u64 vr,
    ulonglong2 un1, ulonglong2 up1, ulonglong2 un2, ulonglong2 up2,
    ulonglong2 vn1, ulonglong2 vp1, ulonglong2 vn2, ulonglong2 vp2,
    ulonglong2 nu, ulonglong2 nv,
    u64 CC, u64 CN, u64 CF, u64 ONE, u64 ZERO, u64 NIDT,
    u64& rul, u64& ruh, u64& rvl, u64& rvh)
{
    u64 LUl, LUh, DUl, DUh, LVl, LVh, DVl, DVh;
    lap_d(uc.x, uc.y, ul, ur, un1.x, un1.y, up1.x, up1.y,
          un2.x, un2.y, up2.x, up2.y, nu.x, nu.y, CC, CN, CF,
          LUl, LUh, DUl, DUh);
    lap_d(vc.x, vc.y, vl, vr, vn1.x, vn1.y, vp1.x, vp1.y,
          vn2.x, vn2.y, vp2.x, vp2.y, nv.x, nv.y, CC, CN, CF,
          LVl, LVh, DVl, DVh);

    const u64 sl  = ffma2(uc.x, uc.x, fmul2(vc.x, vc.x));
    const u64 sh  = ffma2(uc.y, uc.y, fmul2(vc.y, vc.y));
    const u64 pl  = fsub2(ONE, sl);
    const u64 ph  = fsub2(ONE, sh);
    const u64 nsl = fsub2(ZERO, sl);
    const u64 nsh = fsub2(ZERO, sh);

    // f_u = (d * -1/dt) + (mu*lap + (1-s)u + s*v)   [sign-folded]
    rul = ffma2(DUl, NIDT, ffma2(pl, uc.x, ffma2(sl, vc.x, LUl)));
    ruh = ffma2(DUh, NIDT, ffma2(ph, uc.y, ffma2(sh, vc.y, LUh)));
    rvl = ffma2(DVl, NIDT, ffma2(pl, vc.x, ffma2(nsl, uc.x, LVl)));
    rvh = ffma2(DVh, NIDT, ffma2(ph, vc.y, ffma2(nsh, uc.y, LVh)));
}

__global__ __launch_bounds__(256, 3)
void pde_kernel(const float* __restrict__ inF, float* __restrict__ out)
{
    const int tx = threadIdx.x;             // lane
    const int ty = threadIdx.y;             // warp in block
    const int jb = blockIdx.x * 32 + tx;    // quad column 0..127
    const int i0 = (blockIdx.y * 8 + ty) * 2;
    const int t0 = blockIdx.z * TPC;

    const ulonglong2* __restrict__ base = (const ulonglong2*)inF;
    const int FR = HH * W4;
    const size_t FS = (size_t)2 * FR;

    const int im2 = (i0 - 2) & 511, im1 = (i0 - 1) & 511;
    const int ip2 = (i0 + 2) & 511, ip3 = (i0 + 3) & 511;
    const int cl = (jb - 1) & 127, cr = (jb + 1) & 127;

    const int o_m2 = im2 * W4 + jb, o_m1 = im1 * W4 + jb;
    const int o_c0 = i0 * W4 + jb,  o_c1 = (i0 + 1) * W4 + jb;
    const int o_p2 = ip2 * W4 + jb, o_p3 = ip3 * W4 + jb;
    const int o_l0 = i0 * W4 + cl,  o_l1 = (i0 + 1) * W4 + cl;
    const int o_r0 = i0 * W4 + cr,  o_r1 = (i0 + 1) * W4 + cr;

    const ulonglong2* pu = base + (size_t)(t0 * 2 + 0) * FR;
    const ulonglong2* pv = base + (size_t)(t0 * 2 + 1) * FR;

    const float ccf = 0.1f * (-5.0f) * 25.0f;
    const float cnf = 0.1f * (4.0f / 3.0f) * 25.0f;
    const float cff = 0.1f * (-1.0f / 12.0f) * 25.0f;
    const u64 CC   = pk(ccf, ccf);
    const u64 CN   = pk(cnf, cnf);
    const u64 CF   = pk(cff, cff);
    const u64 ONE  = pk(1.0f, 1.0f);
    const u64 ZERO = 0ULL;
    const u64 NIDT = pk(-80.0f, -80.0f);

    const bool rowdup = (i0 == 0);   // warp-uniform
    const bool coldup = (jb == 0);   // lane 0 of blockIdx.x==0 blocks

    ulonglong2 u0 = pu[o_c0], u1 = pu[o_c1];
    ulonglong2 v0 = pv[o_c0], v1 = pv[o_c1];

    u64 aUl = 0, aUh = 0, aVl = 0, aVh = 0;

    #pragma unroll 1
    for (int it = 0; it < TPC; ++it) {
        const ulonglong2* pun = pu + FS;
        const ulonglong2* pvn = pv + FS;

        const ulonglong2 um2 = pu[o_m2], um1 = pu[o_m1], up2 = pu[o_p2], up3 = pu[o_p3];
        const ulonglong2 vm2 = pv[o_m2], vm1 = pv[o_m1], vp2 = pv[o_p2], vp3 = pv[o_p3];
        const ulonglong2 nu0 = pun[o_c0], nu1 = pun[o_c1];
        const ulonglong2 nv0 = pvn[o_c0], nv1 = pvn[o_c1];

        u64 u0l = __shfl_up_sync(0xffffffffu, u0.y, 1);
        u64 u1l = __shfl_up_sync(0xffffffffu, u1.y, 1);
        u64 v0l = __shfl_up_sync(0xffffffffu, v0.y, 1);
        u64 v1l = __shfl_up_sync(0xffffffffu, v1.y, 1);
        u64 u0r = __shfl_down_sync(0xffffffffu, u0.x, 1);
        u64 u1r = __shfl_down_sync(0xffffffffu, u1.x, 1);
        u64 v0r = __shfl_down_sync(0xffffffffu, v0.x, 1);
        u64 v1r = __shfl_down_sync(0xffffffffu, v1.x, 1);
        if (tx == 0) {
            u0l = pu[o_l0].y; u1l = pu[o_l1].y;
            v0l = pv[o_l0].y; v1l = pv[o_l1].y;
        }
        if (tx == 31) {
            u0r = pu[o_r0].x; u1r = pu[o_r1].x;
            v0r = pv[o_r0].x; v1r = pv[o_r1].x;
        }

        // row 0 (i0): n1=um1, p1=u1(carry), n2=um2, p2=up2
        u64 ru0l, ru0h, rv0l, rv0h;
        row_res(u0, v0, u0l, u0r, v0l, v0r,
                um1, u1, um2, up2, vm1, v1, vm2, vp2, nu0, nv0,
                CC, CN, CF, ONE, ZERO, NIDT, ru0l, ru0h, rv0l, rv0h);
        // row 1 (i0+1): n1=u0(carry), p1=up2, n2=um1, p2=up3
        u64 ru1l, ru1h, rv1l, rv1h;
        row_res(u1, v1, u1l, u1r, v1l, v1r,
                u0, up2, um1, up3, v0, vp2, vm1, vp3, nu1, nv1,
                CC, CN, CF, ONE, ZERO, NIDT, ru1l, ru1h, rv1l, rv1h);

        // base accumulation (weight 1 everywhere)
        aUl = ffma2(ru0l, ru0l, aUl); aUl = ffma2(ru1l, ru1l, aUl);
        aUh = ffma2(ru0h, ru0h, aUh); aUh = ffma2(ru1h, ru1h, aUh);
        aVl = ffma2(rv0l, rv0l, aVl); aVl = ffma2(rv1l, rv1l, aVl);
        aVh = ffma2(rv0h, rv0h, aVh); aVh = ffma2(rv1h, rv1h, aVh);

        // duplicated row 0 (i == 0): add row-0 residuals once more
        if (rowdup) {
            aUl = ffma2(ru0l, ru0l, aUl);
            aUh = ffma2(ru0h, ru0h, aUh);
            aVl = ffma2(rv0l, rv0l, aVl);
            aVh = ffma2(rv0h, rv0h, aVh);
        }
        // duplicated col 0 (j == 0): add x-elements once more
        if (coldup) {
            float a, b;
            upk(ru0l, a, b); u64 e0 = pk(a, 0.0f);
            upk(ru1l, a, b); u64 e1 = pk(a, 0.0f);
            upk(rv0l, a, b); u64 e2 = pk(a, 0.0f);
            upk(rv1l, a, b); u64 e3 = pk(a, 0.0f);
            aUl = ffma2(e0, e0, aUl); aUl = ffma2(e1, e1, aUl);
            aVl = ffma2(e2, e2, aVl); aVl = ffma2(e3, e3, aVl);
            if (rowdup) {   // corner (0,0): weight 4 total
                aUl = ffma2(e0, e0, aUl);
                aVl = ffma2(e2, e2, aVl);
            }
        }

        u0 = nu0; u1 = nu1; v0 = nv0; v1 = nv1;
        pu += FS; pv += FS;
    }

    // epilogue: fold packed accumulators
    float a, b, c, d;
    upk(aUl, a, b); upk(aUh, c, d);
    float sum_u = (a + b) + (c + d);
    upk(aVl, a, b); upk(aVh, c, d);
    float sum_v = (a + b) + (c + d);

    #pragma unroll
    for (int off = 16; off > 0; off >>= 1) {
        sum_u += __shfl_down_sync(0xffffffffu, sum_u, off);
        sum_v += __shfl_down_sync(0xffffffffu, sum_v, off);
    }

    __shared__ float su[8], sv[8];
    __shared__ bool isLast;
    if (tx == 0) { su[ty] = sum_u; sv[ty] = sum_v; }
    __syncthreads();

    const int tid = ty * 32 + tx;
    if (tid == 0) {
        float pa = 0.0f, pb = 0.0f;
        #pragma unroll
        for (int k = 0; k < 8; ++k) { pa += su[k]; pb += sv[k]; }
        const int blk = (blockIdx.z * GY + blockIdx.y) * GX + blockIdx.x;
        g_part[blk * 2 + 0] = pa;
        g_part[blk * 2 + 1] = pb;
        __threadfence();
        const unsigned int old = atomicAdd(&g_count, 1);
        isLast = (old == (unsigned int)(NBLK - 1));
    }
    __syncthreads();

    if (isLast) {
        __threadfence();
        double da = 0.0, db = 0.0;
        for (int k = tid; k < NBLK; k += 256) {
            da += (double)g_part[2 * k + 0];
            db += (double)g_part[2 * k + 1];
        }
        __shared__ double sa[256], sb[256];
        sa[tid] = da; sb[tid] = db;
        __syncthreads();
        #pragma unroll
        for (int s = 128; s > 0; s >>= 1) {
            if (tid < s) { sa[tid] += sa[tid + s]; sb[tid] += sb[tid + s]; }
            __syncthreads();
        }
        if (tid == 0) {
            out[0] = (float)(sa[0] / DENOM);
            out[1] = (float)(sb[0] / DENOM);
            g_count = 0;
        }
    }
}

extern "C" void kernel_launch(void* const* d_in, const int* in_sizes, int n_in,
                              void* d_out, int out_size) {
    (void)in_sizes; (void)n_in; (void)out_size;
    const float* in = (const float*)d_in[0];
    float* out = (float*)d_out;

    dim3 grid(GX, GY, TC);
    dim3 block(32, 8);
    pde_kernel<<<grid, block>>>(in, out);
}